// round 4
// baseline (speedup 1.0000x reference)
#include <cuda_runtime.h>
#include <math.h>

// Problem constants (fixed by the dataset)
#define B_   64
#define NPG  1024
#define C_   256
#define EC   48
#define N_   (B_*NPG)        // 65536 nodes
#define E_   (N_*16)         // 1048576 edges
#define EPG  (E_/B_)         // 16384 edges per graph (contiguous)
#define K1   (NPG/2)         // 512 kept after layer 1
#define K2   (NPG/4)         // 256 kept after layer 2
#define ET   128             // edges per tile in edge kernel

typedef unsigned long long u64;

// ---------------- scratch (static device arrays; no allocation) ----------------
__device__ float g_p[N_];        // x @ out_w
__device__ float g_a1[N_];       // x @ sc_w1
__device__ float g_a2[N_];       // x @ sc_w2
__device__ float g_num1[N_];
__device__ float g_cnt1[N_];
__device__ float g_W2[E_];       // edge_attr @ dp_w2 + dp_b2

// float -> order-preserving unsigned (ascending)
__device__ __forceinline__ unsigned fkey(float f) {
    unsigned b = __float_as_uint(f);
    return (b & 0x80000000u) ? ~b : (b | 0x80000000u);
}
__device__ __forceinline__ u64 shflx64(u64 v, int j) {
    return __shfl_xor_sync(0xffffffffu, v, j);
}

// ---------------- hybrid bitonic sort (descending), N = 512 or 1024 ----------------
// Layout: warp w owns 64 consecutive elements; lane holds e[base+lane], e[base+lane+32].
// Stages j<=32 run in registers (shfl / in-thread), j>=64 through shared memory.
template<int N>
__device__ __forceinline__ void sortN(u64* key, int tid) {
    const int lane = tid & 31, warp = tid >> 5, base = warp * 64;
    const bool act = (base < N);
    const int i0 = base + lane, i1 = i0 + 32;

    // Phase 1: k = 2..64 entirely within each warp's 64 elements
    if (act) {
        u64 r0 = key[i0], r1 = key[i1];
#pragma unroll
        for (int k = 2; k <= 64; k <<= 1) {
#pragma unroll
            for (int j = 32; j; j >>= 1) {
                if (j > (k >> 1)) continue;
                if (j == 32) {                       // only when k == 64; up uniform
                    bool up = ((i0 & k) == 0);
                    u64 mx = r0 > r1 ? r0 : r1, mn = r0 > r1 ? r1 : r0;
                    r0 = up ? mx : mn; r1 = up ? mn : mx;
                } else {
                    bool lower = ((lane & j) == 0);
                    bool up0 = ((i0 & k) == 0), up1 = ((i1 & k) == 0);
                    u64 o0 = shflx64(r0, j), o1 = shflx64(r1, j);
                    r0 = ((up0 == lower) ? (r0 > o0 ? r0 : o0) : (r0 < o0 ? r0 : o0));
                    r1 = ((up1 == lower) ? (r1 > o1 ? r1 : o1) : (r1 < o1 ? r1 : o1));
                }
            }
        }
        key[i0] = r0; key[i1] = r1;
    }
    __syncthreads();

    // Phase 2: k = 128..N ; j >= 64 via shared, j <= 32 via registers
    for (int k = 128; k <= N; k <<= 1) {
        for (int j = k >> 1; j >= 64; j >>= 1) {
            if (tid < N / 2) {
                int i = ((tid & ~(j - 1)) << 1) | (tid & (j - 1));
                int p = i | j;
                u64 a = key[i], b = key[p];
                bool up = ((i & k) == 0);
                if (up ? (a < b) : (a > b)) { key[i] = b; key[p] = a; }
            }
            __syncthreads();
        }
        if (act) {
            u64 r0 = key[i0], r1 = key[i1];
            bool up = ((i0 & k) == 0);               // uniform (k >= 128)
            {   // j = 32: partner is the other register, same lane
                u64 mx = r0 > r1 ? r0 : r1, mn = r0 > r1 ? r1 : r0;
                r0 = up ? mx : mn; r1 = up ? mn : mx;
            }
#pragma unroll
            for (int j = 16; j; j >>= 1) {
                bool lower = ((lane & j) == 0);
                u64 o0 = shflx64(r0, j), o1 = shflx64(r1, j);
                r0 = ((up == lower) ? (r0 > o0 ? r0 : o0) : (r0 < o0 ? r0 : o0));
                r1 = ((up == lower) ? (r1 > o1 ? r1 : o1) : (r1 < o1 ? r1 : o1));
            }
            key[i0] = r0; key[i1] = r1;
        }
        __syncthreads();
    }
}

// ---------------- kernels ----------------

// One pass over x: three dot products per row (warp per row, coalesced float4).
// Also zeroes the layer-1 accumulators (replaces a separate zero kernel).
__global__ void k_x(const float* __restrict__ x, const float* __restrict__ scw1,
                    const float* __restrict__ scw2, const float* __restrict__ outw) {
    __shared__ float4 w4[3][C_ / 4];
    int tid = threadIdx.x;
    if (tid < 64)        w4[0][tid]       = ((const float4*)scw1)[tid];
    else if (tid < 128)  w4[1][tid - 64]  = ((const float4*)scw2)[tid - 64];
    else if (tid < 192)  w4[2][tid - 128] = ((const float4*)outw)[tid - 128];
    if (tid < 8) {                                   // zero this block's 8 rows
        g_num1[blockIdx.x * 8 + tid] = 0.f;
        g_cnt1[blockIdx.x * 8 + tid] = 0.f;
    }
    __syncthreads();

    int lane = tid & 31, warp = tid >> 5;
    int row = blockIdx.x * 8 + warp;
    const float4* xr = (const float4*)(x + (size_t)row * C_);
    float d0 = 0.f, d1 = 0.f, d2 = 0.f;
#pragma unroll
    for (int k = 0; k < 2; k++) {
        int c4 = k * 32 + lane;
        float4 v  = xr[c4];
        float4 wa = w4[0][c4], wb = w4[1][c4], wc = w4[2][c4];
        d0 += v.x * wa.x + v.y * wa.y + v.z * wa.z + v.w * wa.w;
        d1 += v.x * wb.x + v.y * wb.y + v.z * wb.z + v.w * wb.w;
        d2 += v.x * wc.x + v.y * wc.y + v.z * wc.z + v.w * wc.w;
    }
#pragma unroll
    for (int o = 16; o; o >>= 1) {
        d0 += __shfl_xor_sync(0xffffffffu, d0, o);
        d1 += __shfl_xor_sync(0xffffffffu, d1, o);
        d2 += __shfl_xor_sync(0xffffffffu, d2, o);
    }
    if (lane == 0) { g_a1[row] = d0; g_a2[row] = d1; g_p[row] = d2; }
}

// One pass over edge_attr: W1, W2 per edge + layer-1 message atomics.
// Tiles staged through shared (padded stride 49 -> conflict-free) so global
// loads are fully coalesced float4s.
__global__ void k_edge(const float* __restrict__ ea, const int* __restrict__ ei,
                       const float* __restrict__ dpw1, const float* __restrict__ dpb1,
                       const float* __restrict__ dpw2, const float* __restrict__ dpb2,
                       const float* __restrict__ scb1) {
    __shared__ float sh[ET][EC + 1];
    __shared__ float w1s[EC], w2s[EC];
    int tid = threadIdx.x;
    if (tid < EC) { w1s[tid] = dpw1[tid]; w2s[tid] = dpw2[tid]; }

    size_t e0 = (size_t)blockIdx.x * ET;
    const float4* ea4 = (const float4*)(ea + e0 * EC);
#pragma unroll
    for (int it = 0; it < (ET * EC / 4) / ET; it++) {   // 12 float4 per thread
        int f = it * ET + tid;
        float4 v = ea4[f];
        int row = f / (EC / 4), c = (f % (EC / 4)) * 4;
        sh[row][c] = v.x; sh[row][c + 1] = v.y; sh[row][c + 2] = v.z; sh[row][c + 3] = v.w;
    }
    __syncthreads();

    float w1 = dpb1[0], w2 = dpb2[0];
#pragma unroll
    for (int j = 0; j < EC; j++) {
        float f = sh[tid][j];
        w1 = fmaf(f, w1s[j], w1);
        w2 = fmaf(f, w2s[j], w2);
    }
    size_t e = e0 + tid;
    g_W2[e] = w2;
    int s = ei[e], d = ei[E_ + e];
    float msg = (g_a1[s] + scb1[0]) * w1;
    atomicAdd(&g_num1[d], msg);
    atomicAdd(&g_cnt1[d], 1.0f);
}

// Fused per-graph kernel: layer-1 scores/top-512, layer-2 message passing with
// SHARED-memory accumulators, layer-2 top-256, final reduction + sigmoid.
// One block per graph, 512 threads.
__global__ void __launch_bounds__(512, 2)
k_graph(const int* __restrict__ ei,
        const float* __restrict__ scb2, const float* __restrict__ outb,
        float* __restrict__ out) {
    __shared__ u64   skey[NPG];       // sort keys (reused for both sorts)
    __shared__ float s_t1[NPG];       // tanh(score1), local node idx
    __shared__ float s_m2[NPG];       // fma(a2, t1, sc_b2) per local node
    __shared__ int   s_map[NPG];      // local node -> layer2 id (or -1)
    __shared__ int   s_perm[K1];      // layer2 id -> local orig idx
    __shared__ float s_num2[K1], s_cnt2[K1];   // later reused as c1 / c2
    __shared__ float red[512];

    const int g = blockIdx.x, tid = threadIdx.x, base = g * NPG;

    // layer-1 scores, keys, t1, m2; p-sum partial (kept in register to the end)
    float ps = g_p[base + tid] + g_p[base + tid + 512];
    const float b2 = scb2[0];
    for (int i = tid; i < NPG; i += 512) {
        float c = g_cnt1[base + i];
        float s = (c > 0.f) ? g_num1[base + i] / c : 0.f;
        float t = tanhf(s);
        s_t1[i] = t;
        s_m2[i] = fmaf(g_a2[base + i], t, b2);
        skey[i] = ((u64)fkey(s) << 32) | (unsigned)(~i);
    }
    if (tid < K1) { s_num2[tid] = 0.f; s_cnt2[tid] = 0.f; }
    __syncthreads();

    sortN<NPG>(skey, tid);

    // build map / perm from sorted ranks (rank = jax perm order)
    for (int pos = tid; pos < NPG; pos += 512) {
        int idx = (int)(~(unsigned)(skey[pos] & 0xffffffffu));
        s_map[idx] = (pos < K1) ? pos : -1;
        if (pos < K1) s_perm[pos] = idx;
    }
    __syncthreads();

    // layer-2 message passing over this graph's contiguous edge slice
    const size_t eb = (size_t)g * EPG;
#pragma unroll 4
    for (int it = 0; it < EPG / 512; it++) {
        size_t e = eb + it * 512 + tid;
        int ls = ei[e] - base, ld = ei[E_ + e] - base;
        int ns = s_map[ls], nd = s_map[ld];
        if ((ns | nd) >= 0) {                        // both kept
            atomicAdd(&s_num2[nd], s_m2[ls] * g_W2[e]);
            atomicAdd(&s_cnt2[nd], 1.0f);
        }
    }
    __syncthreads();

    // layer-2 scores + keys; c1 = p*t1 (all kept-1), c2 = p*t1*t2
    float c1v, c2v;
    {
        int i = tid;                       // tid covers [0, K1)
        float c = s_cnt2[i];
        float sc = (c > 0.f) ? s_num2[i] / c : 0.f;
        int orig = s_perm[i];
        float pc = g_p[base + orig] * s_t1[orig];
        c1v = pc;
        c2v = pc * tanhf(sc);
        skey[i] = ((u64)fkey(sc) << 32) | (unsigned)(~i);
    }
    __syncthreads();
    s_num2[tid] = c1v;                     // reuse as c1
    s_cnt2[tid] = c2v;                     // reuse as c2
    __syncthreads();

    sortN<K1>(skey, tid);

    // positions [0, 256) survive layer 2
    float acc = ps + s_num2[tid];          // S0 partial + c1 for element tid
    if (tid < K2) {
        int idx = (int)(~(unsigned)(skey[tid] & 0xffffffffu));
        acc += s_cnt2[idx];                // c2 of selected node
    }
    red[tid] = acc;
    for (int o = 256; o; o >>= 1) { __syncthreads(); if (tid < o) red[tid] += red[tid + o]; }
    if (tid == 0) {
        float tot = red[0] + outb[0];
        out[g] = 1.f / (1.f + expf(-tot));
    }
}

// ---------------- launch ----------------
extern "C" void kernel_launch(void* const* d_in, const int* in_sizes, int n_in,
                              void* d_out, int out_size) {
    const float* x    = (const float*)d_in[0];
    const int*   ei   = (const int*)  d_in[1];
    const float* ea   = (const float*)d_in[2];
    // d_in[3] = batch (implied by NPG, unused)
    const float* dpw1 = (const float*)d_in[4];
    const float* dpb1 = (const float*)d_in[5];
    const float* scw1 = (const float*)d_in[6];
    const float* scb1 = (const float*)d_in[7];
    const float* dpw2 = (const float*)d_in[8];
    const float* dpb2 = (const float*)d_in[9];
    const float* scw2 = (const float*)d_in[10];
    const float* scb2 = (const float*)d_in[11];
    const float* outw = (const float*)d_in[12];
    const float* outb = (const float*)d_in[13];
    float* out = (float*)d_out;

    k_x    <<<N_ / 8,  256>>>(x, scw1, scw2, outw);
    k_edge <<<E_ / ET, ET >>>(ea, ei, dpw1, dpb1, dpw2, dpb2, scb1);
    k_graph<<<B_,      512>>>(ei, scb2, outb, out);
}